// round 15
// baseline (speedup 1.0000x reference)
#include <cuda_runtime.h>

// SSIM fully-fused, smem-free kernel for GB300 (sm_103a).
// R15 = R10 champion (2 output cols/thread, scalar mid-sum filters, packed
// f32x2 accumulators, full unroll, STRIP_H=16, 6 CTAs/SM = 24 warps) MINUS
// the L2 prefetch pair — single-variable test: at 24 warps/SM the load
// round time exceeds DRAM latency, so the prefetch only burns ~6% of issue
// slots and 2 L1tex wavefronts per iteration.
//
// Algebra (scale-cancelled): with S = 3x3 sum, u = S - 9*center,
//   num = (2*Sx*Sy + 81*C1) * (2*Uxy + 729*C2)
//   den = (Sx^2 + Sy^2 + 81*C1) * (Uss + 729*C2),  Uss = Uxx + Uyy (merged)

#define IMG_H 512
#define IMG_W 960
#define OUT_H 508
#define OUT_W 956
#define W2    (IMG_W / 2)     // row stride in float2 units

#define NTHREADS 128          // 32 lanes x 4 strips
#define STRIP_H 16
#define TILE_W 64             // 32 lanes x 2 cols
#define TILE_H 64             // 4 strips x 16 rows

#define C1S (8.1e-3f)         // 81 * 0.01^2
#define C2S (0.6561f)         // 729 * 0.03^2

typedef unsigned long long u64;

__device__ __forceinline__ u64 PK(float lo, float hi) {
    u64 r; asm("mov.b64 %0, {%1, %2};" : "=l"(r) : "f"(lo), "f"(hi)); return r;
}
__device__ __forceinline__ void UPK(u64 a, float& lo, float& hi) {
    asm("mov.b64 {%0, %1}, %2;" : "=f"(lo), "=f"(hi) : "l"(a));
}
__device__ __forceinline__ u64 PADD(u64 a, u64 b) {
    u64 r; asm("add.rn.f32x2 %0, %1, %2;" : "=l"(r) : "l"(a), "l"(b)); return r;
}
__device__ __forceinline__ u64 PMUL(u64 a, u64 b) {
    u64 r; asm("mul.rn.f32x2 %0, %1, %2;" : "=l"(r) : "l"(a), "l"(b)); return r;
}
__device__ __forceinline__ u64 PFMA(u64 a, u64 b, u64 c) {
    u64 r; asm("fma.rn.f32x2 %0, %1, %2, %3;" : "=l"(r) : "l"(a), "l"(b), "l"(c)); return r;
}

struct St {
    // stage-1 (prev, pairsum) vertical 3-sum state, packed: cols (0,1),(2,3)
    u64 hx0p, hx0s, hx1p, hx1s;
    u64 hy0p, hy0s, hy1p, hy1s;
    // stage-2 (prev, pairsum), packed: output cols (0,1)
    u64 Hssp, Hsss, Hxyp, Hxys;
    // previous-row centers (input cols 1..4)
    float px1, px2, px3, px4;
    float py1, py2, py3, py4;
    // mu sums (S at cols 1,2), one-row history
    float mx0, mx1, my0, my1;
};

// PHASE 0: h-sums + stage-1 accumulate + centers (rows 0,1)
// PHASE 1: + stage-1 S, u, products, stage-2 h-sums (rows 2,3)
// PHASE 2: full, produces output float2
template<int PHASE>
__device__ __forceinline__ void step(St& s,
    float2 a0, float2 a1, float2 a2,
    float2 b0, float2 b1, float2 b2, float2& out)
{
    // input cols 0..5: x = {a0.x,a0.y,a1.x,a1.y,a2.x,a2.y}
    // stage-1 horizontal 3-sums at cols 0..3 via mid-sum identity
    float mxa = a0.y + a1.x;              // x1+x2
    float mxb = a1.y + a2.x;              // x3+x4
    u64 nhx0 = PK(a0.x + mxa, mxa + a1.y);   // h(0), h(1)
    u64 nhx1 = PK(a1.x + mxb, mxb + a2.y);   // h(2), h(3)

    float mya = b0.y + b1.x;
    float myb = b1.y + b2.x;
    u64 nhy0 = PK(b0.x + mya, mya + b1.y);
    u64 nhy1 = PK(b1.x + myb, myb + b2.y);

    if (PHASE >= 1) {
        // stage-1 vertical 3-sums (packed)
        u64 Sx0 = PADD(nhx0, s.hx0s);
        u64 Sx1 = PADD(nhx1, s.hx1s);
        u64 Sy0 = PADD(nhy0, s.hy0s);
        u64 Sy1 = PADD(nhy1, s.hy1s);

        float Sx0l, Sx0h, Sx1l, Sx1h, Sy0l, Sy0h, Sy1l, Sy1h;
        UPK(Sx0, Sx0l, Sx0h); UPK(Sx1, Sx1l, Sx1h);
        UPK(Sy0, Sy0l, Sy0h); UPK(Sy1, Sy1l, Sy1h);

        // u = S - 9*center (scalar FFMA with immediate; centers = prev row)
        u64 UXa = PK(fmaf(s.px1, -9.0f, Sx0l), fmaf(s.px2, -9.0f, Sx0h));
        u64 UXb = PK(fmaf(s.px3, -9.0f, Sx1l), fmaf(s.px4, -9.0f, Sx1h));
        u64 UYa = PK(fmaf(s.py1, -9.0f, Sy0l), fmaf(s.py2, -9.0f, Sy0h));
        u64 UYb = PK(fmaf(s.py3, -9.0f, Sy1l), fmaf(s.py4, -9.0f, Sy1h));

        // products (packed): ss = ux^2 + uy^2 (merged), xy = ux*uy
        u64 tssa = PFMA(UYa, UYa, PMUL(UXa, UXa));
        u64 tssb = PFMA(UYb, UYb, PMUL(UXb, UXb));
        u64 txya = PMUL(UXa, UYa);
        u64 txyb = PMUL(UXb, UYb);

        // stage-2 horizontal 3-sums (scalar mid-sum) for output cols 0,1
        float t0, t1, t2, t3, z0, z1, z2, z3;
        UPK(tssa, t0, t1); UPK(tssb, t2, t3);
        UPK(txya, z0, z1); UPK(txyb, z2, z3);
        float mT = t1 + t2;
        u64 nHss = PK(t0 + mT, mT + t3);
        float mZ = z1 + z2;
        u64 nHxy = PK(z0 + mZ, mZ + z3);

        if (PHASE == 2) {
            // stage-2 vertical 3-sums
            u64 Uss = PADD(nHss, s.Hsss);
            u64 Uxy = PADD(nHxy, s.Hxys);

            float US0, US1, UXY0, UXY1;
            UPK(Uss, US0, US1); UPK(Uxy, UXY0, UXY1);

            // scalar SSIM per output column
            float n1_0 = fmaf(s.mx0 * s.my0, 2.0f, C1S);
            float n1_1 = fmaf(s.mx1 * s.my1, 2.0f, C1S);
            float d1_0 = fmaf(s.my0, s.my0, fmaf(s.mx0, s.mx0, C1S));
            float d1_1 = fmaf(s.my1, s.my1, fmaf(s.mx1, s.mx1, C1S));
            float n2_0 = fmaf(UXY0, 2.0f, C2S);
            float n2_1 = fmaf(UXY1, 2.0f, C2S);
            float d2_0 = US0 + C2S;
            float d2_1 = US1 + C2S;

            out.x = fminf(fmaxf(1.0f - __fdividef(n1_0 * n2_0, d1_0 * d2_0), 0.0f), 2.0f);
            out.y = fminf(fmaxf(1.0f - __fdividef(n1_1 * n2_1, d1_1 * d2_1), 0.0f), 2.0f);
        }

        // stage-2 accumulator updates
        s.Hsss = PADD(nHss, s.Hssp);  s.Hssp = nHss;
        s.Hxys = PADD(nHxy, s.Hxyp);  s.Hxyp = nHxy;

        // mu sums for next row's output: S at cols 1,2
        s.mx0 = Sx0h; s.mx1 = Sx1l;
        s.my0 = Sy0h; s.my1 = Sy1l;
    }

    // stage-1 accumulator updates (every row)
    s.hx0s = PADD(nhx0, s.hx0p);  s.hx0p = nhx0;
    s.hx1s = PADD(nhx1, s.hx1p);  s.hx1p = nhx1;
    s.hy0s = PADD(nhy0, s.hy0p);  s.hy0p = nhy0;
    s.hy1s = PADD(nhy1, s.hy1p);  s.hy1p = nhy1;

    // centers for the next stage-1 row (input cols 1..4)
    s.px1 = a0.y; s.px2 = a1.x; s.px3 = a1.y; s.px4 = a2.x;
    s.py1 = b0.y; s.py2 = b1.x; s.py3 = b1.y; s.py4 = b2.x;
}

__global__ __launch_bounds__(NTHREADS, 6)
void ssim_kernel(const float* __restrict__ X,
                 const float* __restrict__ Y,
                 float* __restrict__ O)
{
    const int tid   = threadIdx.x;
    const int lane  = tid & 31;
    const int strip = tid >> 5;
    const int img   = blockIdx.z;
    const int oy0   = blockIdx.y * TILE_H + strip * STRIP_H;
    const int ox    = blockIdx.x * TILE_W + 2 * lane;
    const int cx    = min(ox, IMG_W - 6);   // clamp reads (even); mask outputs
    const bool col_ok = (ox < OUT_W);

    const float2* __restrict__ X2 =
        (const float2*)(X + (size_t)img * (IMG_H * IMG_W) + cx);
    const float2* __restrict__ Y2 =
        (const float2*)(Y + (size_t)img * (IMG_H * IMG_W) + cx);
    float* __restrict__ Ob = O + (size_t)img * (OUT_H * OUT_W) + ox;

    St s;
    s.hx0p = s.hx0s = s.hx1p = s.hx1s = 0;
    s.hy0p = s.hy0s = s.hy1p = s.hy1s = 0;
    s.Hssp = s.Hsss = s.Hxyp = s.Hxys = 0;
    s.px1 = s.px2 = s.px3 = s.px4 = 0.0f;
    s.py1 = s.py2 = s.py3 = s.py4 = 0.0f;
    s.mx0 = s.mx1 = s.my0 = s.my1 = 0.0f;

    float2 out;
    #pragma unroll
    for (int t = 0; t < STRIP_H + 4; ++t) {
        const int gy = min(oy0 + t, IMG_H - 1);
        const int ro = gy * W2;

        float2 a0 = __ldg(X2 + ro), a1 = __ldg(X2 + ro + 1), a2 = __ldg(X2 + ro + 2);
        float2 b0 = __ldg(Y2 + ro), b1 = __ldg(Y2 + ro + 1), b2 = __ldg(Y2 + ro + 2);

        if (t < 2)      step<0>(s, a0, a1, a2, b0, b1, b2, out);
        else if (t < 4) step<1>(s, a0, a1, a2, b0, b1, b2, out);
        else {
            step<2>(s, a0, a1, a2, b0, b1, b2, out);
            const int oy = oy0 + t - 4;
            if (col_ok && oy < OUT_H) {
                *(float2*)(Ob + (size_t)oy * OUT_W) = out;
            }
        }
    }
}

extern "C" void kernel_launch(void* const* d_in, const int* in_sizes, int n_in,
                              void* d_out, int out_size)
{
    const float* x = (const float*)d_in[0];
    const float* y = (const float*)d_in[1];
    float* o = (float*)d_out;

    dim3 grid((OUT_W + TILE_W - 1) / TILE_W,   // 15
              (OUT_H + TILE_H - 1) / TILE_H,   // 8
              48);                             // 16 batch * 3 channels
    ssim_kernel<<<grid, NTHREADS>>>(x, y, o);
}

// round 16
// speedup vs baseline: 1.2880x; 1.2880x over previous
#include <cuda_runtime.h>

// SSIM fully-fused, smem-free kernel for GB300 (sm_103a).
// R16 = R10 champion (2 output cols/thread, scalar mid-sum filters, packed
// f32x2 accumulators, full unroll, STRIP_H=16, 6 CTAs/SM = 24 warps) with
// the L2 prefetch upgraded to an L1 prefetch (same 4-row distance):
// R15 proved the prefetch converts DRAM-latency loads to L2-latency loads
// (worth 17us); this converts them to L1-hit loads (~39 cyc).
//
// Algebra (scale-cancelled): with S = 3x3 sum, u = S - 9*center,
//   num = (2*Sx*Sy + 81*C1) * (2*Uxy + 729*C2)
//   den = (Sx^2 + Sy^2 + 81*C1) * (Uss + 729*C2),  Uss = Uxx + Uyy (merged)

#define IMG_H 512
#define IMG_W 960
#define OUT_H 508
#define OUT_W 956
#define W2    (IMG_W / 2)     // row stride in float2 units

#define NTHREADS 128          // 32 lanes x 4 strips
#define STRIP_H 16
#define TILE_W 64             // 32 lanes x 2 cols
#define TILE_H 64             // 4 strips x 16 rows

#define C1S (8.1e-3f)         // 81 * 0.01^2
#define C2S (0.6561f)         // 729 * 0.03^2

typedef unsigned long long u64;

__device__ __forceinline__ u64 PK(float lo, float hi) {
    u64 r; asm("mov.b64 %0, {%1, %2};" : "=l"(r) : "f"(lo), "f"(hi)); return r;
}
__device__ __forceinline__ void UPK(u64 a, float& lo, float& hi) {
    asm("mov.b64 {%0, %1}, %2;" : "=f"(lo), "=f"(hi) : "l"(a));
}
__device__ __forceinline__ u64 PADD(u64 a, u64 b) {
    u64 r; asm("add.rn.f32x2 %0, %1, %2;" : "=l"(r) : "l"(a), "l"(b)); return r;
}
__device__ __forceinline__ u64 PMUL(u64 a, u64 b) {
    u64 r; asm("mul.rn.f32x2 %0, %1, %2;" : "=l"(r) : "l"(a), "l"(b)); return r;
}
__device__ __forceinline__ u64 PFMA(u64 a, u64 b, u64 c) {
    u64 r; asm("fma.rn.f32x2 %0, %1, %2, %3;" : "=l"(r) : "l"(a), "l"(b), "l"(c)); return r;
}
#define PREF_L1(p) asm volatile("prefetch.global.L1 [%0];" :: "l"(p))

struct St {
    // stage-1 (prev, pairsum) vertical 3-sum state, packed: cols (0,1),(2,3)
    u64 hx0p, hx0s, hx1p, hx1s;
    u64 hy0p, hy0s, hy1p, hy1s;
    // stage-2 (prev, pairsum), packed: output cols (0,1)
    u64 Hssp, Hsss, Hxyp, Hxys;
    // previous-row centers (input cols 1..4)
    float px1, px2, px3, px4;
    float py1, py2, py3, py4;
    // mu sums (S at cols 1,2), one-row history
    float mx0, mx1, my0, my1;
};

// PHASE 0: h-sums + stage-1 accumulate + centers (rows 0,1)
// PHASE 1: + stage-1 S, u, products, stage-2 h-sums (rows 2,3)
// PHASE 2: full, produces output float2
template<int PHASE>
__device__ __forceinline__ void step(St& s,
    float2 a0, float2 a1, float2 a2,
    float2 b0, float2 b1, float2 b2, float2& out)
{
    // input cols 0..5: x = {a0.x,a0.y,a1.x,a1.y,a2.x,a2.y}
    // stage-1 horizontal 3-sums at cols 0..3 via mid-sum identity
    float mxa = a0.y + a1.x;              // x1+x2
    float mxb = a1.y + a2.x;              // x3+x4
    u64 nhx0 = PK(a0.x + mxa, mxa + a1.y);   // h(0), h(1)
    u64 nhx1 = PK(a1.x + mxb, mxb + a2.y);   // h(2), h(3)

    float mya = b0.y + b1.x;
    float myb = b1.y + b2.x;
    u64 nhy0 = PK(b0.x + mya, mya + b1.y);
    u64 nhy1 = PK(b1.x + myb, myb + b2.y);

    if (PHASE >= 1) {
        // stage-1 vertical 3-sums (packed)
        u64 Sx0 = PADD(nhx0, s.hx0s);
        u64 Sx1 = PADD(nhx1, s.hx1s);
        u64 Sy0 = PADD(nhy0, s.hy0s);
        u64 Sy1 = PADD(nhy1, s.hy1s);

        float Sx0l, Sx0h, Sx1l, Sx1h, Sy0l, Sy0h, Sy1l, Sy1h;
        UPK(Sx0, Sx0l, Sx0h); UPK(Sx1, Sx1l, Sx1h);
        UPK(Sy0, Sy0l, Sy0h); UPK(Sy1, Sy1l, Sy1h);

        // u = S - 9*center (scalar FFMA with immediate; centers = prev row)
        u64 UXa = PK(fmaf(s.px1, -9.0f, Sx0l), fmaf(s.px2, -9.0f, Sx0h));
        u64 UXb = PK(fmaf(s.px3, -9.0f, Sx1l), fmaf(s.px4, -9.0f, Sx1h));
        u64 UYa = PK(fmaf(s.py1, -9.0f, Sy0l), fmaf(s.py2, -9.0f, Sy0h));
        u64 UYb = PK(fmaf(s.py3, -9.0f, Sy1l), fmaf(s.py4, -9.0f, Sy1h));

        // products (packed): ss = ux^2 + uy^2 (merged), xy = ux*uy
        u64 tssa = PFMA(UYa, UYa, PMUL(UXa, UXa));
        u64 tssb = PFMA(UYb, UYb, PMUL(UXb, UXb));
        u64 txya = PMUL(UXa, UYa);
        u64 txyb = PMUL(UXb, UYb);

        // stage-2 horizontal 3-sums (scalar mid-sum) for output cols 0,1
        float t0, t1, t2, t3, z0, z1, z2, z3;
        UPK(tssa, t0, t1); UPK(tssb, t2, t3);
        UPK(txya, z0, z1); UPK(txyb, z2, z3);
        float mT = t1 + t2;
        u64 nHss = PK(t0 + mT, mT + t3);
        float mZ = z1 + z2;
        u64 nHxy = PK(z0 + mZ, mZ + z3);

        if (PHASE == 2) {
            // stage-2 vertical 3-sums
            u64 Uss = PADD(nHss, s.Hsss);
            u64 Uxy = PADD(nHxy, s.Hxys);

            float US0, US1, UXY0, UXY1;
            UPK(Uss, US0, US1); UPK(Uxy, UXY0, UXY1);

            // scalar SSIM per output column
            float n1_0 = fmaf(s.mx0 * s.my0, 2.0f, C1S);
            float n1_1 = fmaf(s.mx1 * s.my1, 2.0f, C1S);
            float d1_0 = fmaf(s.my0, s.my0, fmaf(s.mx0, s.mx0, C1S));
            float d1_1 = fmaf(s.my1, s.my1, fmaf(s.mx1, s.mx1, C1S));
            float n2_0 = fmaf(UXY0, 2.0f, C2S);
            float n2_1 = fmaf(UXY1, 2.0f, C2S);
            float d2_0 = US0 + C2S;
            float d2_1 = US1 + C2S;

            out.x = fminf(fmaxf(1.0f - __fdividef(n1_0 * n2_0, d1_0 * d2_0), 0.0f), 2.0f);
            out.y = fminf(fmaxf(1.0f - __fdividef(n1_1 * n2_1, d1_1 * d2_1), 0.0f), 2.0f);
        }

        // stage-2 accumulator updates
        s.Hsss = PADD(nHss, s.Hssp);  s.Hssp = nHss;
        s.Hxys = PADD(nHxy, s.Hxyp);  s.Hxyp = nHxy;

        // mu sums for next row's output: S at cols 1,2
        s.mx0 = Sx0h; s.mx1 = Sx1l;
        s.my0 = Sy0h; s.my1 = Sy1l;
    }

    // stage-1 accumulator updates (every row)
    s.hx0s = PADD(nhx0, s.hx0p);  s.hx0p = nhx0;
    s.hx1s = PADD(nhx1, s.hx1p);  s.hx1p = nhx1;
    s.hy0s = PADD(nhy0, s.hy0p);  s.hy0p = nhy0;
    s.hy1s = PADD(nhy1, s.hy1p);  s.hy1p = nhy1;

    // centers for the next stage-1 row (input cols 1..4)
    s.px1 = a0.y; s.px2 = a1.x; s.px3 = a1.y; s.px4 = a2.x;
    s.py1 = b0.y; s.py2 = b1.x; s.py3 = b1.y; s.py4 = b2.x;
}

__global__ __launch_bounds__(NTHREADS, 6)
void ssim_kernel(const float* __restrict__ X,
                 const float* __restrict__ Y,
                 float* __restrict__ O)
{
    const int tid   = threadIdx.x;
    const int lane  = tid & 31;
    const int strip = tid >> 5;
    const int img   = blockIdx.z;
    const int oy0   = blockIdx.y * TILE_H + strip * STRIP_H;
    const int ox    = blockIdx.x * TILE_W + 2 * lane;
    const int cx    = min(ox, IMG_W - 6);   // clamp reads (even); mask outputs
    const bool col_ok = (ox < OUT_W);

    const float2* __restrict__ X2 =
        (const float2*)(X + (size_t)img * (IMG_H * IMG_W) + cx);
    const float2* __restrict__ Y2 =
        (const float2*)(Y + (size_t)img * (IMG_H * IMG_W) + cx);
    float* __restrict__ Ob = O + (size_t)img * (OUT_H * OUT_W) + ox;

    St s;
    s.hx0p = s.hx0s = s.hx1p = s.hx1s = 0;
    s.hy0p = s.hy0s = s.hy1p = s.hy1s = 0;
    s.Hssp = s.Hsss = s.Hxyp = s.Hxys = 0;
    s.px1 = s.px2 = s.px3 = s.px4 = 0.0f;
    s.py1 = s.py2 = s.py3 = s.py4 = 0.0f;
    s.mx0 = s.mx1 = s.my0 = s.my1 = 0.0f;

    float2 out;
    #pragma unroll
    for (int t = 0; t < STRIP_H + 4; ++t) {
        const int gy = min(oy0 + t, IMG_H - 1);
        const int ro = gy * W2;

        float2 a0 = __ldg(X2 + ro), a1 = __ldg(X2 + ro + 1), a2 = __ldg(X2 + ro + 2);
        float2 b0 = __ldg(Y2 + ro), b1 = __ldg(Y2 + ro + 1), b2 = __ldg(Y2 + ro + 2);

        if (t + 4 < STRIP_H + 4) {
            const int pgy = min(oy0 + t + 4, IMG_H - 1);
            PREF_L1((const float*)(X2 + pgy * W2));
            PREF_L1((const float*)(Y2 + pgy * W2));
        }

        if (t < 2)      step<0>(s, a0, a1, a2, b0, b1, b2, out);
        else if (t < 4) step<1>(s, a0, a1, a2, b0, b1, b2, out);
        else {
            step<2>(s, a0, a1, a2, b0, b1, b2, out);
            const int oy = oy0 + t - 4;
            if (col_ok && oy < OUT_H) {
                *(float2*)(Ob + (size_t)oy * OUT_W) = out;
            }
        }
    }
}

extern "C" void kernel_launch(void* const* d_in, const int* in_sizes, int n_in,
                              void* d_out, int out_size)
{
    const float* x = (const float*)d_in[0];
    const float* y = (const float*)d_in[1];
    float* o = (float*)d_out;

    dim3 grid((OUT_W + TILE_W - 1) / TILE_W,   // 15
              (OUT_H + TILE_H - 1) / TILE_H,   // 8
              48);                             // 16 batch * 3 channels
    ssim_kernel<<<grid, NTHREADS>>>(x, y, o);
}